// round 7
// baseline (speedup 1.0000x reference)
#include <cuda_runtime.h>
#include <cstdint>

#define S_TOTAL 524288
#define ROW_F 48          // N_OBJ * N_PROP floats per s-row

// out layout: action_probs (2, S, 3) then p_values (2, 28, S)
__global__ __launch_bounds__(256)
void ump_kernel(const float* __restrict__ x,
                const float* __restrict__ action,
                const unsigned char* __restrict__ mask,
                const float* __restrict__ pb,
                float* __restrict__ out)
{
    const size_t S = (size_t)S_TOTAL;
    int t = blockIdx.x * blockDim.x + threadIdx.x;
    int s0 = t * 2;
    if (s0 >= S_TOTAL) return;

    const float* row0 = x + (size_t)s0 * ROW_F;
    const float* row1 = row0 + ROW_F;

    // front-batched: 16 independent LDG.64 (props 0,1 of 8 objects, 2 rows)
    float2 va[8], vb[8];
#pragma unroll
    for (int j = 0; j < 8; j++) {
        va[j] = *reinterpret_cast<const float2*>(row0 + j * 6);
        vb[j] = *reinterpret_cast<const float2*>(row1 + j * 6);
    }

    // combined interval (both predicate flags true)
    float lo = fmaxf(pb[0], pb[2]);
    float hi = fminf(pb[1], pb[3]);

    float* __restrict__ pv = out + 6 * S;

    bool any_a = false, any_b = false;
    bool ee_a = true, ee_b = true;

#pragma unroll
    for (int p = 0; p < 7; p++) {
        float a0 = fabsf(va[0].x - va[p + 1].x);
        float a1 = fabsf(va[0].y - va[p + 1].y);
        float b0 = fabsf(vb[0].x - vb[p + 1].x);
        float b1 = fabsf(vb[0].y - vb[p + 1].y);

        any_a = any_a || (a0 >= lo && a0 <= hi) || (a1 >= lo && a1 <= hi);
        any_b = any_b || (b0 >= lo && b0 <= hi) || (b1 >= lo && b1 <= hi);
        ee_a = ee_a && (va[p + 1].y > 0.8f);
        ee_b = ee_b && (vb[p + 1].y > 0.8f);

        float2 d0 = make_float2(a0, b0);   // prop-0 distances for s0, s0+1
        float2 d1 = make_float2(a1, b1);   // prop-1

        size_t r = (size_t)p * 4;
        // rows p*4+{0,1}=d0, p*4+{2,3}=d1; duplicated at +28 (second type slice)
        *reinterpret_cast<float2*>(pv + (r + 0)  * S + s0) = d0;
        *reinterpret_cast<float2*>(pv + (r + 1)  * S + s0) = d0;
        *reinterpret_cast<float2*>(pv + (r + 2)  * S + s0) = d1;
        *reinterpret_cast<float2*>(pv + (r + 3)  * S + s0) = d1;
        *reinterpret_cast<float2*>(pv + (r + 28) * S + s0) = d0;
        *reinterpret_cast<float2*>(pv + (r + 29) * S + s0) = d0;
        *reinterpret_cast<float2*>(pv + (r + 30) * S + s0) = d1;
        *reinterpret_cast<float2*>(pv + (r + 31) * S + s0) = d1;
    }

    // existence + action_probs
    bool m0 = mask[0] != 0;
    bool m1 = mask[1] != 0;
    float ac0 = action[0], ac1 = action[1], ac2 = action[2];
    float an0 = ac0 / (ac0 + 1e-20f);
    float an1 = ac1 / (ac1 + 1e-20f);
    float an2 = ac2 / (ac2 + 1e-20f);

    bool sat_a = any_a && ((va[0].x > 0.8f) == m0) && (ee_a == m1);
    bool sat_b = any_b && ((vb[0].x > 0.8f) == m0) && (ee_b == m1);

    // 6 contiguous floats starting at s0*3 (s0 even -> 8B aligned)
    float2 w01 = make_float2(sat_a ? an0 : 0.0f, sat_a ? an1 : 0.0f);
    float2 w23 = make_float2(sat_a ? an2 : 0.0f, sat_b ? an0 : 0.0f);
    float2 w45 = make_float2(sat_b ? an1 : 0.0f, sat_b ? an2 : 0.0f);

    float* ap0 = out + (size_t)s0 * 3;
    float* ap1 = ap0 + 3 * S;
    *reinterpret_cast<float2*>(ap0 + 0) = w01;
    *reinterpret_cast<float2*>(ap0 + 2) = w23;
    *reinterpret_cast<float2*>(ap0 + 4) = w45;
    *reinterpret_cast<float2*>(ap1 + 0) = w01;
    *reinterpret_cast<float2*>(ap1 + 2) = w23;
    *reinterpret_cast<float2*>(ap1 + 4) = w45;
}

extern "C" void kernel_launch(void* const* d_in, const int* in_sizes, int n_in,
                              void* d_out, int out_size)
{
    const float* x = (const float*)d_in[0];
    const float* action = (const float*)d_in[1];
    const unsigned char* mask = (const unsigned char*)d_in[2];
    const float* pb = (const float*)d_in[3];
    float* out = (float*)d_out;

    int threads = 256;
    int total_threads = S_TOTAL / 2;
    int blocks = (total_threads + threads - 1) / threads;
    ump_kernel<<<blocks, threads>>>(x, action, mask, pb, out);
}

// round 8
// speedup vs baseline: 1.2134x; 1.2134x over previous
#include <cuda_runtime.h>
#include <cstdint>

#define S_TOTAL 524288
#define N_PROP 6
#define N_OBJ 8

// out layout: action_probs (2, S, 3) then p_values (2, 28, S)
__global__ __launch_bounds__(256)
void ump_kernel(const float* __restrict__ x,
                const float* __restrict__ action,
                const unsigned char* __restrict__ mask,
                const float* __restrict__ pb,
                float* __restrict__ out)
{
    const int s = blockIdx.x * 256 + threadIdx.x;   // grid exactly covers S_TOTAL

    const float* row = x + (size_t)s * (N_OBJ * N_PROP);

    // props 0,1 of each of the 8 objects: 8 independent LDG.64, front-batched
    float2 v[N_OBJ];
#pragma unroll
    for (int j = 0; j < N_OBJ; j++) {
        v[j] = *reinterpret_cast<const float2*>(row + j * N_PROP);
    }

    // existence
    bool enemy_exist = true;
#pragma unroll
    for (int j = 1; j < N_OBJ; j++) enemy_exist = enemy_exist && (v[j].y > 0.8f);
    bool m0 = mask[0] != 0;
    bool m1 = mask[1] != 0;
    bool exist_satisfy = ((v[0].x > 0.8f) == m0) && (enemy_exist == m1);

    // combined interval (both predicate flags true in this problem instance)
    float lo = fmaxf(pb[0], pb[2]);
    float hi = fminf(pb[1], pb[3]);

    float d[7][2];
    bool any_sat = false;
#pragma unroll
    for (int p = 0; p < 7; p++) {
        float d0 = fabsf(v[0].x - v[p + 1].x);
        float d1 = fabsf(v[0].y - v[p + 1].y);
        d[p][0] = d0;
        d[p][1] = d1;
        any_sat = any_sat || (d0 >= lo && d0 <= hi) || (d1 >= lo && d1 <= hi);
    }
    bool satisfies = any_sat && exist_satisfy;

    float a0 = action[0], a1 = action[1], a2 = action[2];
    float w0 = satisfies ? (a0 / (a0 + 1e-20f)) : 0.0f;
    float w1 = satisfies ? (a1 / (a1 + 1e-20f)) : 0.0f;
    float w2 = satisfies ? (a2 / (a2 + 1e-20f)) : 0.0f;

    // 32-bit addressing: total output = 62*S floats = 130 MB < 2^31 bytes
    const unsigned int S = S_TOTAL;

    // action_probs: [t, s, c] — identical for both type slices
    {
        unsigned int base0 = (unsigned int)s * 3u;
        unsigned int base1 = base0 + 3u * S;
        out[base0 + 0] = w0; out[base0 + 1] = w1; out[base0 + 2] = w2;
        out[base1 + 0] = w0; out[base1 + 1] = w1; out[base1 + 2] = w2;
    }

    // p_values: offset 6S, shape (2, 28, S); row = p*4 + k*2 + j, value d[p][k]
    float* __restrict__ pv = out + 6u * S;
    unsigned int idx0 = (unsigned int)s;   // row 0 element for this s
#pragma unroll
    for (int p = 0; p < 7; p++) {
#pragma unroll
        for (int k = 0; k < 2; k++) {
            float val = d[p][k];
            unsigned int r = (unsigned int)(p * 4 + k * 2);
            pv[idx0 + (r + 0u) * S] = val;
            pv[idx0 + (r + 1u) * S] = val;
            pv[idx0 + (r + 28u) * S] = val;
            pv[idx0 + (r + 29u) * S] = val;
        }
    }
}

extern "C" void kernel_launch(void* const* d_in, const int* in_sizes, int n_in,
                              void* d_out, int out_size)
{
    const float* x = (const float*)d_in[0];
    const float* action = (const float*)d_in[1];
    const unsigned char* mask = (const unsigned char*)d_in[2];
    const float* pb = (const float*)d_in[3];
    float* out = (float*)d_out;

    ump_kernel<<<S_TOTAL / 256, 256>>>(x, action, mask, pb, out);
}